// round 7
// baseline (speedup 1.0000x reference)
#include <cuda_runtime.h>
#include <cuda_fp16.h>
#include <mma.h>
#include <cstdint>

using namespace nvcuda;

// ---------------------------------------------------------------------------
// Problem constants
// ---------------------------------------------------------------------------
#define FH 128
#define FW 128
#define NPIX (FH*FW)       // 16384
#define QN 65536           // queries
#define SN (4*QN)          // 262144 corner samples
#define K1 585             // valid unfold dims
#define K0P 608            // padded K for layer0 (mult of 32)
#define NH 256

// ---------------------------------------------------------------------------
// Scratch
// ---------------------------------------------------------------------------
__device__ __align__(128) __half g_X[NPIX * K0P];
__device__ __align__(128) __half g_Wt0[NH * K0P];      // [256][608] f16 (transposed)
__device__ __align__(128) __half g_Wt1[NH * NH];
__device__ __align__(128) __half g_Wt2[NH * NH];
__device__ __align__(128) __half g_Wt3[NH * NH];
__device__ __align__(128) float  g_hp[NPIX * NH];      // raw layer-0 acc (no bias)
__device__ __align__(128) float  g_bufA[(size_t)SN * NH];  // raw layer-1 acc
__device__ __align__(128) float  g_bufB[(size_t)SN * NH];  // raw layer-2 acc
__device__ __align__(128) float  g_pred[SN * 3];

// ---------------------------------------------------------------------------
// Helpers
// ---------------------------------------------------------------------------
__device__ __forceinline__ uint32_t smem_u32(const void* p) {
    uint32_t a;
    asm("{ .reg .u64 t; cvta.to.shared.u64 t, %1; cvt.u32.u64 %0, t; }" : "=r"(a) : "l"(p));
    return a;
}
__device__ __forceinline__ void cp16(uint32_t dst, const void* src) {
    asm volatile("cp.async.cg.shared.global [%0], [%1], 16;" :: "r"(dst), "l"(src));
}
#define CP_COMMIT() asm volatile("cp.async.commit_group;" ::: "memory")
#define CP_WAIT(n)  asm volatile("cp.async.wait_group %0;" :: "n"(n) : "memory")

// ---------------------------------------------------------------------------
// GEMM geometry: BM=128, BN=128, BK=32, 256 threads, warps 2(m) x 4(n),
// warp tile 64x32 = wmma 4m x 2n of 16x16x16.
// SMEM tile: 128 rows x 40 halves (32 data + 8 pad) = 10240 B per stage.
// Row stride 80 B: 16B-aligned for cp.async; conflict-free for ldmatrix rows.
// ---------------------------------------------------------------------------
#define ROWH 40
#define STGB (128 * ROWH * 2)          // 10240
#define SMEM_GEMM (4 * STGB)           // 40960: A0,A1,B0,B1
#define SMEM_L1   (SMEM_GEMM + 1536)   // + idx/r0/r1
#define SMEM_L3   (65536 + 3072)       // 64KB C-tile region + W4

typedef wmma::fragment<wmma::accumulator, 16, 16, 16, float> AccFrag;

// cp.async loader for a f16 source [rows][K] -> stage (A for layer0, B always)
__device__ __forceinline__ void cp_stage(uint32_t base, const __half* __restrict__ src,
                                         size_t row0, int K, int k0, int tid) {
#pragma unroll
    for (int i = 0; i < 2; i++) {
        int li = tid + i * 256;           // 0..511
        int m = li >> 2, c = li & 3;      // row, 16B chunk
        cp16(base + m * 80 + c * 16, src + (row0 + m) * (size_t)K + k0 + c * 8);
    }
}

// fill A stage from fp32 source with fused bias+relu+f16 round
__device__ __forceinline__ void fill_stage(char* smem, int stg,
                                           const float* __restrict__ src,
                                           const float* __restrict__ bias,
                                           size_t bm, int k0, int tid) {
#pragma unroll
    for (int i = 0; i < 4; i++) {
        int li = tid + i * 256;           // 0..1023
        int m = li >> 3, c = li & 7;      // row, 4-float group
        float4 s = __ldg((const float4*)(src + (bm + m) * 256 + k0 + c * 4));
        float4 b = __ldg((const float4*)(bias + k0 + c * 4));
        __half2 lo = __floats2half2_rn(fmaxf(s.x + b.x, 0.f), fmaxf(s.y + b.y, 0.f));
        __half2 hi = __floats2half2_rn(fmaxf(s.z + b.z, 0.f), fmaxf(s.w + b.w, 0.f));
        uint2 o;
        o.x = *reinterpret_cast<uint32_t*>(&lo);
        o.y = *reinterpret_cast<uint32_t*>(&hi);
        *reinterpret_cast<uint2*>(smem + stg * STGB + m * 80 + c * 8) = o;
    }
}

// one BK=32 stage of wmma MMAs
__device__ __forceinline__ void mma_stage(char* smem, int stg, int wm, int wn,
                                          AccFrag (&cf)[4][2]) {
    const __half* sA = (const __half*)(smem + stg * STGB);
    const __half* sB = (const __half*)(smem + 2 * STGB + stg * STGB);
#pragma unroll
    for (int ks = 0; ks < 2; ks++) {
        wmma::fragment<wmma::matrix_b, 16, 16, 16, __half, wmma::col_major> bf0, bf1;
        wmma::load_matrix_sync(bf0, sB + (wn * 32) * ROWH + ks * 16, ROWH);
        wmma::load_matrix_sync(bf1, sB + (wn * 32 + 16) * ROWH + ks * 16, ROWH);
#pragma unroll
        for (int mt = 0; mt < 4; mt++) {
            wmma::fragment<wmma::matrix_a, 16, 16, 16, __half, wmma::row_major> af;
            wmma::load_matrix_sync(af, sA + (wm * 64 + mt * 16) * ROWH + ks * 16, ROWH);
            wmma::mma_sync(cf[mt][0], af, bf0, cf[mt][0]);
            wmma::mma_sync(cf[mt][1], af, bf1, cf[mt][1]);
        }
    }
}

__device__ __forceinline__ void store_raw(AccFrag (&cf)[4][2], float* __restrict__ C,
                                          size_t bm, int bn, int wm, int wn) {
#pragma unroll
    for (int mt = 0; mt < 4; mt++)
#pragma unroll
        for (int nt = 0; nt < 2; nt++)
            wmma::store_matrix_sync(
                C + (bm + wm * 64 + mt * 16) * 256 + bn + wn * 32 + nt * 16,
                cf[mt][nt], 256, wmma::mem_row_major);
}

// ---------------------------------------------------------------------------
// Layer 0: hp = X(f16) @ Wt0^T (raw acc; b0 fused into layer-1 fill)
// ---------------------------------------------------------------------------
__global__ __launch_bounds__(256, 2) void gemm_l0(const __half* __restrict__ X,
                                                  const __half* __restrict__ Bt,
                                                  float* __restrict__ C) {
    extern __shared__ char smem[];
    uint32_t sb = smem_u32(smem);
    const int tid = threadIdx.x;
    const int wid = tid >> 5, wm = wid >> 2, wn = wid & 3;
    const size_t bm = (size_t)blockIdx.x * 128;
    const int bn = blockIdx.y * 128;
    const int nit = K0P / 32;           // 19

    AccFrag cf[4][2];
#pragma unroll
    for (int mt = 0; mt < 4; mt++)
#pragma unroll
        for (int nt = 0; nt < 2; nt++) wmma::fill_fragment(cf[mt][nt], 0.f);

    cp_stage(sb, X, bm, K0P, 0, tid);
    cp_stage(sb + 2 * STGB, Bt, bn, K0P, 0, tid);
    CP_COMMIT();
    cp_stage(sb + STGB, X, bm, K0P, 32, tid);
    cp_stage(sb + 3 * STGB, Bt, bn, K0P, 32, tid);
    CP_COMMIT();

    for (int it = 0; it < nit; it++) {
        if (it + 1 < nit) { CP_WAIT(1); } else { CP_WAIT(0); }
        __syncthreads();
        mma_stage(smem, it & 1, wm, wn, cf);
        __syncthreads();
        if (it + 2 < nit) {
            cp_stage(sb + (it & 1) * STGB, X, bm, K0P, (it + 2) * 32, tid);
            cp_stage(sb + (2 + (it & 1)) * STGB, Bt, bn, K0P, (it + 2) * 32, tid);
            CP_COMMIT();
        }
    }
    store_raw(cf, C, bm, bn, wm, wn);
}

// ---------------------------------------------------------------------------
// Corner geometry (proven)
// ---------------------------------------------------------------------------
__device__ __forceinline__ void corner_calc(float c0, float c1, int cc,
                                            int& idx, float& rel0, float& rel1) {
    const float rr = 1.0f / 128.0f;
    float vx = (cc & 2) ? 1.f : -1.f;
    float vy = (cc & 1) ? 1.f : -1.f;
    float cy = fminf(fmaxf(c0 + vx * rr + 1e-6f, -1.f + 1e-6f), 1.f - 1e-6f);
    float cx = fminf(fmaxf(c1 + vy * rr + 1e-6f, -1.f + 1e-6f), 1.f - 1e-6f);
    int iy = (int)rintf(((cy + 1.0f) * 128.0f - 1.0f) * 0.5f);
    int ix = (int)rintf(((cx + 1.0f) * 128.0f - 1.0f) * 0.5f);
    iy = min(max(iy, 0), 127);
    ix = min(max(ix, 0), 127);
    float qy = -1.0f + (2.0f * (float)iy + 1.0f) / 128.0f;
    float qx = -1.0f + (2.0f * (float)ix + 1.0f) / 128.0f;
    rel0 = (c0 - qy) * 128.0f;
    rel1 = (c1 - qx) * 128.0f;
    idx = iy * 128 + ix;
}

// ---------------------------------------------------------------------------
// Layer 1: A = f16(relu(hp[idx] + b0 + r0*W0[585] + r1*W0[586])); C raw -> bufA
// ---------------------------------------------------------------------------
__global__ __launch_bounds__(256, 2) void gemm_l1(const float* __restrict__ hr,
                                                  const float* __restrict__ W0,
                                                  const float* __restrict__ b0,
                                                  const __half* __restrict__ Bt,
                                                  float* __restrict__ C) {
    extern __shared__ char smem[];
    uint32_t sb = smem_u32(smem);
    int*   sIdx = (int*)(smem + SMEM_GEMM);
    float* sR0  = (float*)(smem + SMEM_GEMM + 512);
    float* sR1  = (float*)(smem + SMEM_GEMM + 1024);
    const int tid = threadIdx.x;
    const int wid = tid >> 5, wm = wid >> 2, wn = wid & 3;
    const size_t bm = (size_t)blockIdx.x * 128;
    const int bn = blockIdx.y * 128;
    const int nit = 8;

    if (tid < 128) {
        size_t s = bm + tid;
        int cc = (int)(s >> 16);
        int q  = (int)(s & 65535);
        float c0 = hr[2 * q], c1 = hr[2 * q + 1];
        int idx; float r0, r1;
        corner_calc(c0, c1, cc, idx, r0, r1);
        sIdx[tid] = idx; sR0[tid] = r0; sR1[tid] = r1;
    }
    __syncthreads();

    AccFrag cf[4][2];
#pragma unroll
    for (int mt = 0; mt < 4; mt++)
#pragma unroll
        for (int nt = 0; nt < 2; nt++) wmma::fill_fragment(cf[mt][nt], 0.f);

    // A fill with gather
    auto fillg = [&](int stg, int k0) {
#pragma unroll
        for (int i = 0; i < 4; i++) {
            int li = tid + i * 256;
            int m = li >> 3, c = li & 7;
            int row = sIdx[m];
            float r0 = sR0[m], r1 = sR1[m];
            float4 h  = __ldg((const float4*)&g_hp[(size_t)row * 256 + k0 + c * 4]);
            float4 wa = __ldg((const float4*)&W0[585 * 256 + k0 + c * 4]);
            float4 wb = __ldg((const float4*)&W0[586 * 256 + k0 + c * 4]);
            float4 bb = __ldg((const float4*)&b0[k0 + c * 4]);
            __half2 lo = __floats2half2_rn(fmaxf(h.x + bb.x + r0 * wa.x + r1 * wb.x, 0.f),
                                           fmaxf(h.y + bb.y + r0 * wa.y + r1 * wb.y, 0.f));
            __half2 hi = __floats2half2_rn(fmaxf(h.z + bb.z + r0 * wa.z + r1 * wb.z, 0.f),
                                           fmaxf(h.w + bb.w + r0 * wa.w + r1 * wb.w, 0.f));
            uint2 o;
            o.x = *reinterpret_cast<uint32_t*>(&lo);
            o.y = *reinterpret_cast<uint32_t*>(&hi);
            *reinterpret_cast<uint2*>(smem + stg * STGB + m * 80 + c * 8) = o;
        }
    };

    fillg(0, 0);
    cp_stage(sb + 2 * STGB, Bt, bn, 256, 0, tid);
    CP_COMMIT();
    fillg(1, 32);
    cp_stage(sb + 3 * STGB, Bt, bn, 256, 32, tid);
    CP_COMMIT();

    for (int it = 0; it < nit; it++) {
        if (it + 1 < nit) { CP_WAIT(1); } else { CP_WAIT(0); }
        __syncthreads();
        mma_stage(smem, it & 1, wm, wn, cf);
        __syncthreads();
        if (it + 2 < nit) {
            fillg(it & 1, (it + 2) * 32);
            cp_stage(sb + (2 + (it & 1)) * STGB, Bt, bn, 256, (it + 2) * 32, tid);
            CP_COMMIT();
        }
    }
    store_raw(cf, C, bm, bn, wm, wn);
}

// ---------------------------------------------------------------------------
// Layer 2: A = f16(relu(bufA + b1)); C raw -> bufB
// ---------------------------------------------------------------------------
__global__ __launch_bounds__(256, 2) void gemm_l2(const float* __restrict__ Aprev,
                                                  const float* __restrict__ bias,
                                                  const __half* __restrict__ Bt,
                                                  float* __restrict__ C) {
    extern __shared__ char smem[];
    uint32_t sb = smem_u32(smem);
    const int tid = threadIdx.x;
    const int wid = tid >> 5, wm = wid >> 2, wn = wid & 3;
    const size_t bm = (size_t)blockIdx.x * 128;
    const int bn = blockIdx.y * 128;
    const int nit = 8;

    AccFrag cf[4][2];
#pragma unroll
    for (int mt = 0; mt < 4; mt++)
#pragma unroll
        for (int nt = 0; nt < 2; nt++) wmma::fill_fragment(cf[mt][nt], 0.f);

    fill_stage(smem, 0, Aprev, bias, bm, 0, tid);
    cp_stage(sb + 2 * STGB, Bt, bn, 256, 0, tid);
    CP_COMMIT();
    fill_stage(smem, 1, Aprev, bias, bm, 32, tid);
    cp_stage(sb + 3 * STGB, Bt, bn, 256, 32, tid);
    CP_COMMIT();

    for (int it = 0; it < nit; it++) {
        if (it + 1 < nit) { CP_WAIT(1); } else { CP_WAIT(0); }
        __syncthreads();
        mma_stage(smem, it & 1, wm, wn, cf);
        __syncthreads();
        if (it + 2 < nit) {
            fill_stage(smem, it & 1, Aprev, bias, bm, (it + 2) * 32, tid);
            cp_stage(sb + (2 + (it & 1)) * STGB, Bt, bn, 256, (it + 2) * 32, tid);
            CP_COMMIT();
        }
    }
    store_raw(cf, C, bm, bn, wm, wn);
}

// ---------------------------------------------------------------------------
// Layer 3 + final fused: A = f16(relu(bufB + b2)); h4 = relu(acc + b3);
// atomicAdd(g_pred[m][c], sum_n h4[m][n]*W4[n][c])
// ---------------------------------------------------------------------------
__global__ __launch_bounds__(256, 2) void gemm_l3(const float* __restrict__ Aprev,
                                                  const float* __restrict__ b2,
                                                  const __half* __restrict__ Bt,
                                                  const float* __restrict__ b3,
                                                  const float* __restrict__ W4) {
    extern __shared__ char smem[];
    uint32_t sb = smem_u32(smem);
    float* sW4 = (float*)(smem + 65536);
    const int tid = threadIdx.x;
    const int wid = tid >> 5, wm = wid >> 2, wn = wid & 3;
    const size_t bm = (size_t)blockIdx.x * 128;
    const int bn = blockIdx.y * 128;
    const int nit = 8;

    if (tid < 256) {
        sW4[tid * 3 + 0] = W4[tid * 3 + 0];
        sW4[tid * 3 + 1] = W4[tid * 3 + 1];
        sW4[tid * 3 + 2] = W4[tid * 3 + 2];
    }
    __syncthreads();

    AccFrag cf[4][2];
#pragma unroll
    for (int mt = 0; mt < 4; mt++)
#pragma unroll
        for (int nt = 0; nt < 2; nt++) wmma::fill_fragment(cf[mt][nt], 0.f);

    fill_stage(smem, 0, Aprev, b2, bm, 0, tid);
    cp_stage(sb + 2 * STGB, Bt, bn, 256, 0, tid);
    CP_COMMIT();
    fill_stage(smem, 1, Aprev, b2, bm, 32, tid);
    cp_stage(sb + 3 * STGB, Bt, bn, 256, 32, tid);
    CP_COMMIT();

    for (int it = 0; it < nit; it++) {
        if (it + 1 < nit) { CP_WAIT(1); } else { CP_WAIT(0); }
        __syncthreads();
        mma_stage(smem, it & 1, wm, wn, cf);
        __syncthreads();
        if (it + 2 < nit) {
            fill_stage(smem, it & 1, Aprev, b2, bm, (it + 2) * 32, tid);
            cp_stage(sb + (2 + (it & 1)) * STGB, Bt, bn, 256, (it + 2) * 32, tid);
            CP_COMMIT();
        }
    }

    // dump C tile (128x128 f32) into smem: per-warp 64x32 slots
    float* sC = (float*)smem;
    __syncthreads();
#pragma unroll
    for (int mt = 0; mt < 4; mt++)
#pragma unroll
        for (int nt = 0; nt < 2; nt++)
            wmma::store_matrix_sync(sC + wid * 2048 + mt * 16 * 32 + nt * 16,
                                    cf[mt][nt], 32, wmma::mem_row_major);
    __syncthreads();

    // final dot: thread handles (row = tid>>1, 64 cols)
    int row = tid >> 1;
    int half = tid & 1;
    float p0 = 0.f, p1 = 0.f, p2 = 0.f;
#pragma unroll 8
    for (int jj = 0; jj < 64; jj++) {
        int col = half * 64 + jj;
        int w_m = row >> 6, w_n = col >> 5;
        float v = sC[(w_m * 4 + w_n) * 2048 + (row & 63) * 32 + (col & 31)];
        v = fmaxf(v + __ldg(&b3[bn + col]), 0.f);
        const float* w = &sW4[(bn + col) * 3];
        p0 += v * w[0];
        p1 += v * w[1];
        p2 += v * w[2];
    }
    p0 += __shfl_xor_sync(0xFFFFFFFFu, p0, 1);
    p1 += __shfl_xor_sync(0xFFFFFFFFu, p1, 1);
    p2 += __shfl_xor_sync(0xFFFFFFFFu, p2, 1);
    if (half == 0) {
        size_t m = bm + row;
        atomicAdd(&g_pred[m * 3 + 0], p0);
        atomicAdd(&g_pred[m * 3 + 1], p1);
        atomicAdd(&g_pred[m * 3 + 2], p2);
    }
}

// ---------------------------------------------------------------------------
// prep kernels
// ---------------------------------------------------------------------------
__global__ void build_X(const float* __restrict__ mf, const float* __restrict__ mask) {
    int p = blockIdx.x;
    int t = threadIdx.x;
    if (t >= K0P) return;
    int y = p >> 7, x = p & 127;
    float v = 0.f;
    if (t < K1) {
        int c = t / 9, r = t - c * 9;
        int ki = r / 3, kj = r - ki * 3;
        int yy = y + ki - 1, xx = x + kj - 1;
        if (yy >= 0 && yy < FH && xx >= 0 && xx < FW) {
            v = (c < 64) ? mf[(c << 14) + (yy << 7) + xx] : mask[(yy << 7) + xx];
        }
    }
    g_X[p * K0P + t] = __float2half_rn(v);
}

__global__ void prep_wt(const float* __restrict__ W, __half* __restrict__ Wt,
                        int Kp, int Kv) {
    int i = blockIdx.x * blockDim.x + threadIdx.x;
    if (i >= 256 * Kp) return;
    int n = i / Kp, k = i - n * Kp;
    Wt[i] = __float2half_rn((k < Kv) ? W[k * 256 + n] : 0.f);
}

__global__ void zero_pred() {
    int i = blockIdx.x * blockDim.x + threadIdx.x;
    if (i < SN * 3) g_pred[i] = 0.f;
}

// ---------------------------------------------------------------------------
// local ensemble (adds b4; g_pred holds raw W4-dot sums)
// ---------------------------------------------------------------------------
__global__ void ensemble(const float* __restrict__ hr, const float* __restrict__ b4,
                         float* __restrict__ out) {
    int q = blockIdx.x * blockDim.x + threadIdx.x;
    if (q >= QN) return;
    float c0 = hr[2 * q], c1 = hr[2 * q + 1];
    float b40 = __ldg(&b4[0]), b41 = __ldg(&b4[1]), b42 = __ldg(&b4[2]);
    float area[4];
#pragma unroll
    for (int cc = 0; cc < 4; cc++) {
        int idx; float r0, r1;
        corner_calc(c0, c1, cc, idx, r0, r1);
        area[cc] = fabsf(r0 * r1) + 1e-9f;
    }
    float tot = area[0] + area[1] + area[2] + area[3];
    float o0 = 0.f, o1 = 0.f, o2 = 0.f;
#pragma unroll
    for (int cc = 0; cc < 4; cc++) {
        float w = area[3 - cc] / tot;
        size_t s = (size_t)cc * QN + q;
        o0 += (g_pred[s * 3 + 0] + b40) * w;
        o1 += (g_pred[s * 3 + 1] + b41) * w;
        o2 += (g_pred[s * 3 + 2] + b42) * w;
    }
    out[0 * QN + q] = o0;
    out[1 * QN + q] = o1;
    out[2 * QN + q] = o2;
}

// ---------------------------------------------------------------------------
// Launch
// ---------------------------------------------------------------------------
extern "C" void kernel_launch(void* const* d_in, const int* in_sizes, int n_in,
                              void* d_out, int out_size) {
    const float* mf   = (const float*)d_in[0];
    const float* mask = (const float*)d_in[1];
    const float* hr = (const float*)d_in[3];
    const float* W0 = (const float*)d_in[4];
    const float* b0 = (const float*)d_in[5];
    const float* W1 = (const float*)d_in[6];
    const float* b1 = (const float*)d_in[7];
    const float* W2 = (const float*)d_in[8];
    const float* b2 = (const float*)d_in[9];
    const float* W3 = (const float*)d_in[10];
    const float* b3 = (const float*)d_in[11];
    const float* W4 = (const float*)d_in[12];
    const float* b4 = (const float*)d_in[13];
    float* out = (float*)d_out;

    void *pX, *pWt0, *pWt1, *pWt2, *pWt3, *pHp, *pA, *pB;
    cudaGetSymbolAddress(&pX,   g_X);
    cudaGetSymbolAddress(&pWt0, g_Wt0);
    cudaGetSymbolAddress(&pWt1, g_Wt1);
    cudaGetSymbolAddress(&pWt2, g_Wt2);
    cudaGetSymbolAddress(&pWt3, g_Wt3);
    cudaGetSymbolAddress(&pHp,  g_hp);
    cudaGetSymbolAddress(&pA,   g_bufA);
    cudaGetSymbolAddress(&pB,   g_bufB);

    cudaFuncSetAttribute(gemm_l0, cudaFuncAttributeMaxDynamicSharedMemorySize, SMEM_GEMM);
    cudaFuncSetAttribute(gemm_l1, cudaFuncAttributeMaxDynamicSharedMemorySize, SMEM_L1);
    cudaFuncSetAttribute(gemm_l2, cudaFuncAttributeMaxDynamicSharedMemorySize, SMEM_GEMM);
    cudaFuncSetAttribute(gemm_l3, cudaFuncAttributeMaxDynamicSharedMemorySize, SMEM_L3);

    build_X<<<NPIX, K0P>>>(mf, mask);
    prep_wt<<<(256 * K0P + 255) / 256, 256>>>(W0, (__half*)pWt0, K0P, K1);
    prep_wt<<<256, 256>>>(W1, (__half*)pWt1, 256, 256);
    prep_wt<<<256, 256>>>(W2, (__half*)pWt2, 256, 256);
    prep_wt<<<256, 256>>>(W3, (__half*)pWt3, 256, 256);
    zero_pred<<<(SN * 3 + 255) / 256, 256>>>();

    gemm_l0<<<dim3(NPIX / 128, 2), 256, SMEM_GEMM>>>((const __half*)pX,
                                                     (const __half*)pWt0, (float*)pHp);

    gemm_l1<<<dim3(SN / 128, 2), 256, SMEM_L1>>>(hr, W0, b0, (const __half*)pWt1, (float*)pA);

    gemm_l2<<<dim3(SN / 128, 2), 256, SMEM_GEMM>>>((const float*)pA, b1,
                                                   (const __half*)pWt2, (float*)pB);

    gemm_l3<<<dim3(SN / 128, 2), 256, SMEM_L3>>>((const float*)pB, b2,
                                                 (const __half*)pWt3, b3, W4);

    ensemble<<<QN / 256, 256>>>(hr, b4, out);
}

// round 8
// speedup vs baseline: 1.3484x; 1.3484x over previous
#include <cuda_runtime.h>
#include <cstdint>

// ---------------------------------------------------------------------------
// Problem constants
// ---------------------------------------------------------------------------
#define FH 128
#define FW 128
#define NPIX (FH*FW)       // 16384
#define QN 65536           // queries
#define SN (4*QN)          // 262144 corner samples
#define K1 585             // valid unfold dims
#define K0P 608            // padded K for layer0 (mult of 32)
#define NH 256

// ---------------------------------------------------------------------------
// Scratch (fp32 everywhere — proven path)
// ---------------------------------------------------------------------------
__device__ __align__(128) float g_X[NPIX * K0P];
__device__ __align__(128) float g_Wt0[NH * K0P];
__device__ __align__(128) float g_Wt1[NH * NH];
__device__ __align__(128) float g_Wt2[NH * NH];
__device__ __align__(128) float g_Wt3[NH * NH];
__device__ __align__(128) float g_hp[NPIX * NH];
__device__ __align__(128) float g_bufA[(size_t)SN * NH];
__device__ __align__(128) float g_bufB[(size_t)SN * NH];
__device__ __align__(128) float g_pred[SN * 3];

// ---------------------------------------------------------------------------
// PTX helpers (compute_103-portable) — R3/R6-proven
// ---------------------------------------------------------------------------
__device__ __forceinline__ uint32_t smem_u32(const void* p) {
    uint32_t a;
    asm("{ .reg .u64 t; cvta.to.shared.u64 t, %1; cvt.u32.u64 %0, t; }" : "=r"(a) : "l"(p));
    return a;
}
__device__ __forceinline__ float rnd_tf32(float x) {
    uint32_t r;
    asm("cvt.rna.tf32.f32 %0, %1;" : "=r"(r) : "f"(x));
    return __uint_as_float(r);
}
__device__ __forceinline__ void cp16(uint32_t dst, const void* src) {
    asm volatile("cp.async.cg.shared.global [%0], [%1], 16;" :: "r"(dst), "l"(src));
}
#define CP_COMMIT() asm volatile("cp.async.commit_group;" ::: "memory")
#define CP_WAIT(n)  asm volatile("cp.async.wait_group %0;" :: "n"(n) : "memory")

__device__ __forceinline__ void ldsm4(uint32_t* r, uint32_t addr) {
    asm volatile("ldmatrix.sync.aligned.m8n8.x4.shared.b16 {%0,%1,%2,%3}, [%4];"
                 : "=r"(r[0]), "=r"(r[1]), "=r"(r[2]), "=r"(r[3]) : "r"(addr));
}
__device__ __forceinline__ void mma_tf32(float* d, const uint32_t* a, const uint32_t* b) {
    asm volatile(
        "mma.sync.aligned.m16n8k8.row.col.f32.tf32.tf32.f32 "
        "{%0,%1,%2,%3}, {%4,%5,%6,%7}, {%8,%9}, {%0,%1,%2,%3};"
        : "+f"(d[0]), "+f"(d[1]), "+f"(d[2]), "+f"(d[3])
        : "r"(a[0]), "r"(a[1]), "r"(a[2]), "r"(a[3]), "r"(b[0]), "r"(b[1]));
}

// ---------------------------------------------------------------------------
// GEMM geometry: BM=128, BN=128, BK=32, 256 thr, warps 2(m) x 4(n)
// 3-stage pipeline: A stages [0..2], B stages [3..5], 16KB each.
// ---------------------------------------------------------------------------
#define AST 16384
#define NST 3
#define B_BASE (NST * AST)
#define SMEM_GEMM (2 * NST * AST)            // 98304
#define SMEM_L1   (SMEM_GEMM + 1536)
#define SMEM_L3   (SMEM_GEMM + 3072)

__device__ __forceinline__ uint32_t swzo(int r, int c) {
    return (uint32_t)(r * 128 + ((c ^ (r & 7)) << 4));
}

__device__ __forceinline__ void load_A(uint32_t sb, const float* __restrict__ A,
                                       size_t bm, int k0, int stg, int K, int tid) {
    uint32_t ab = sb + stg * AST;
#pragma unroll
    for (int i = 0; i < 4; i++) {
        int li = tid + i * 256;
        int m = li >> 3, c = li & 7;
        cp16(ab + swzo(m, c), A + (bm + m) * (size_t)K + k0 + c * 4);
    }
}
__device__ __forceinline__ void load_B(uint32_t sb, const float* __restrict__ Bt,
                                       int bn, int k0, int stg, int K, int tid) {
    uint32_t bb = sb + B_BASE + stg * AST;
#pragma unroll
    for (int i = 0; i < 4; i++) {
        int li = tid + i * 256;
        int n = li >> 3, c = li & 7;
        cp16(bb + swzo(n, c), Bt + (size_t)(bn + n) * K + k0 + c * 4);
    }
}

struct LdsmGeom { int a_r, a_c, b_r, b_c; };
__device__ __forceinline__ LdsmGeom make_geom(int lane, int wm, int wn) {
    LdsmGeom g;
    int rw = lane & 7;
    int j  = lane >> 3;
    g.a_r = wm * 64 + rw + (j & 1) * 8;
    g.a_c = j >> 1;
    g.b_r = wn * 32 + rw + (j >> 1) * 8;
    g.b_c = j & 1;
    return g;
}

__device__ __forceinline__ void mma_block(float acc[4][4][4], uint32_t abase,
                                          uint32_t bbase, const LdsmGeom& g) {
#pragma unroll
    for (int ks = 0; ks < 4; ks++) {
        uint32_t afr[4][4];
#pragma unroll
        for (int mt = 0; mt < 4; mt++)
            ldsm4(afr[mt], abase + swzo(g.a_r + mt * 16, ks * 2 + g.a_c));
        uint32_t bfr[2][4];
#pragma unroll
        for (int gg = 0; gg < 2; gg++)
            ldsm4(bfr[gg], bbase + swzo(g.b_r + gg * 16, ks * 2 + g.b_c));
#pragma unroll
        for (int mt = 0; mt < 4; mt++)
#pragma unroll
            for (int nt = 0; nt < 4; nt++)
                mma_tf32(acc[mt][nt], afr[mt], &bfr[nt >> 1][(nt & 1) * 2]);
    }
}

// ---------------------------------------------------------------------------
// Generic GEMM: grid (2, M/128) — bn fast so the bn-pair shares A via L2.
// ---------------------------------------------------------------------------
__global__ __launch_bounds__(256, 2) void gemm_tf32(const float* __restrict__ A,
                                                    const float* __restrict__ Bt,
                                                    const float* __restrict__ bias,
                                                    float* __restrict__ C,
                                                    int K, int relu, int rnd) {
    extern __shared__ char smem[];
    uint32_t sb = smem_u32(smem);
    const int tid = threadIdx.x;
    const int wid = tid >> 5;
    const int lane = tid & 31;
    const int wm = wid >> 2;
    const int wn = wid & 3;
    const size_t bm = (size_t)blockIdx.y * 128;
    const int bn = blockIdx.x * 128;
    const int nit = K >> 5;

    float acc[4][4][4];
#pragma unroll
    for (int i = 0; i < 4; i++)
#pragma unroll
        for (int j = 0; j < 4; j++)
#pragma unroll
            for (int v = 0; v < 4; v++) acc[i][j][v] = 0.f;

    load_A(sb, A, bm, 0, 0, K, tid);  load_B(sb, Bt, bn, 0, 0, K, tid);  CP_COMMIT();
    load_A(sb, A, bm, 32, 1, K, tid); load_B(sb, Bt, bn, 32, 1, K, tid); CP_COMMIT();

    LdsmGeom geo = make_geom(lane, wm, wn);

    for (int it = 0; it < nit; it++) {
        if (it + 1 < nit) { CP_WAIT(1); } else { CP_WAIT(0); }
        __syncthreads();
        if (it + 2 < nit) {
            int stg = (it + 2) % NST;
            load_A(sb, A, bm, (it + 2) * 32, stg, K, tid);
            load_B(sb, Bt, bn, (it + 2) * 32, stg, K, tid);
            CP_COMMIT();
        }
        int stg = it % NST;
        mma_block(acc, sb + stg * AST, sb + B_BASE + stg * AST, geo);
    }

    const int er = lane >> 2;
    const int ec = (lane & 3) * 2;
#pragma unroll
    for (int mt = 0; mt < 4; mt++) {
#pragma unroll
        for (int nt = 0; nt < 4; nt++) {
            int n = bn + wn * 32 + nt * 8 + ec;
            float bi0 = __ldg(&bias[n]);
            float bi1 = __ldg(&bias[n + 1]);
            size_t m0 = bm + wm * 64 + mt * 16 + er;
            float v0 = acc[mt][nt][0] + bi0;
            float v1 = acc[mt][nt][1] + bi1;
            float v2 = acc[mt][nt][2] + bi0;
            float v3 = acc[mt][nt][3] + bi1;
            if (relu) {
                v0 = fmaxf(v0, 0.f); v1 = fmaxf(v1, 0.f);
                v2 = fmaxf(v2, 0.f); v3 = fmaxf(v3, 0.f);
            }
            if (rnd) {
                v0 = rnd_tf32(v0); v1 = rnd_tf32(v1);
                v2 = rnd_tf32(v2); v3 = rnd_tf32(v3);
            }
            *reinterpret_cast<float2*>(&C[m0 * 256 + n])       = make_float2(v0, v1);
            *reinterpret_cast<float2*>(&C[(m0 + 8) * 256 + n]) = make_float2(v2, v3);
        }
    }
}

// ---------------------------------------------------------------------------
// Corner geometry (proven)
// ---------------------------------------------------------------------------
__device__ __forceinline__ void corner_calc(float c0, float c1, int cc,
                                            int& idx, float& rel0, float& rel1) {
    const float rr = 1.0f / 128.0f;
    float vx = (cc & 2) ? 1.f : -1.f;
    float vy = (cc & 1) ? 1.f : -1.f;
    float cy = fminf(fmaxf(c0 + vx * rr + 1e-6f, -1.f + 1e-6f), 1.f - 1e-6f);
    float cx = fminf(fmaxf(c1 + vy * rr + 1e-6f, -1.f + 1e-6f), 1.f - 1e-6f);
    int iy = (int)rintf(((cy + 1.0f) * 128.0f - 1.0f) * 0.5f);
    int ix = (int)rintf(((cx + 1.0f) * 128.0f - 1.0f) * 0.5f);
    iy = min(max(iy, 0), 127);
    ix = min(max(ix, 0), 127);
    float qy = -1.0f + (2.0f * (float)iy + 1.0f) / 128.0f;
    float qx = -1.0f + (2.0f * (float)ix + 1.0f) / 128.0f;
    rel0 = (c0 - qy) * 128.0f;
    rel1 = (c1 - qx) * 128.0f;
    idx = iy * 128 + ix;
}

// ---------------------------------------------------------------------------
// Layer-1 GEMM with fused assemble (A built in smem; B via cp.async)
// ---------------------------------------------------------------------------
__global__ __launch_bounds__(256, 2) void gemm_l1(const float* __restrict__ hr,
                                                  const float* __restrict__ W0,
                                                  const float* __restrict__ Bt,
                                                  const float* __restrict__ bias,
                                                  float* __restrict__ C) {
    extern __shared__ char smem[];
    uint32_t sb = smem_u32(smem);
    int*   sIdx = (int*)(smem + SMEM_GEMM);
    float* sR0  = (float*)(smem + SMEM_GEMM + 512);
    float* sR1  = (float*)(smem + SMEM_GEMM + 1024);
    const int tid = threadIdx.x;
    const int wid = tid >> 5;
    const int lane = tid & 31;
    const int wm = wid >> 2;
    const int wn = wid & 3;
    const size_t bm = (size_t)blockIdx.y * 128;
    const int bn = blockIdx.x * 128;
    const int nit = 8;

    if (tid < 128) {
        size_t s = bm + tid;
        int cc = (int)(s >> 16);
        int q  = (int)(s & 65535);
        float c0 = hr[2 * q], c1 = hr[2 * q + 1];
        int idx; float r0, r1;
        corner_calc(c0, c1, cc, idx, r0, r1);
        sIdx[tid] = idx; sR0[tid] = r0; sR1[tid] = r1;
    }
    __syncthreads();

    float acc[4][4][4];
#pragma unroll
    for (int i = 0; i < 4; i++)
#pragma unroll
        for (int j = 0; j < 4; j++)
#pragma unroll
            for (int v = 0; v < 4; v++) acc[i][j][v] = 0.f;

    auto fillg = [&](int stg, int k0) {
#pragma unroll
        for (int i = 0; i < 4; i++) {
            int li = tid + i * 256;
            int m = li >> 3, c = li & 7;
            int row = sIdx[m];
            float r0 = sR0[m], r1 = sR1[m];
            float4 h  = __ldg((const float4*)&g_hp[(size_t)row * 256 + k0 + c * 4]);
            float4 wa = __ldg((const float4*)&W0[585 * 256 + k0 + c * 4]);
            float4 wb = __ldg((const float4*)&W0[586 * 256 + k0 + c * 4]);
            float4 o;
            o.x = rnd_tf32(fmaxf(h.x + r0 * wa.x + r1 * wb.x, 0.f));
            o.y = rnd_tf32(fmaxf(h.y + r0 * wa.y + r1 * wb.y, 0.f));
            o.z = rnd_tf32(fmaxf(h.z + r0 * wa.z + r1 * wb.z, 0.f));
            o.w = rnd_tf32(fmaxf(h.w + r0 * wa.w + r1 * wb.w, 0.f));
            *reinterpret_cast<float4*>(smem + stg * AST + swzo(m, c)) = o;
        }
    };

    fillg(0, 0);  load_B(sb, Bt, bn, 0, 0, 256, tid);  CP_COMMIT();
    fillg(1, 32); load_B(sb, Bt, bn, 32, 1, 256, tid); CP_COMMIT();

    LdsmGeom geo = make_geom(lane, wm, wn);

    for (int it = 0; it < nit; it++) {
        if (it + 1 < nit) { CP_WAIT(1); } else { CP_WAIT(0); }
        __syncthreads();
        if (it + 2 < nit) {
            int stg = (it + 2) % NST;
            fillg(stg, (it + 2) * 32);
            load_B(sb, Bt, bn, (it + 2) * 32, stg, 256, tid);
            CP_COMMIT();
        }
        int stg = it % NST;
        mma_block(acc, sb + stg * AST, sb + B_BASE + stg * AST, geo);
    }

    const int er = lane >> 2;
    const int ec = (lane & 3) * 2;
#pragma unroll
    for (int mt = 0; mt < 4; mt++) {
#pragma unroll
        for (int nt = 0; nt < 4; nt++) {
            int n = bn + wn * 32 + nt * 8 + ec;
            float bi0 = __ldg(&bias[n]);
            float bi1 = __ldg(&bias[n + 1]);
            size_t m0 = bm + wm * 64 + mt * 16 + er;
            float v0 = rnd_tf32(fmaxf(acc[mt][nt][0] + bi0, 0.f));
            float v1 = rnd_tf32(fmaxf(acc[mt][nt][1] + bi1, 0.f));
            float v2 = rnd_tf32(fmaxf(acc[mt][nt][2] + bi0, 0.f));
            float v3 = rnd_tf32(fmaxf(acc[mt][nt][3] + bi1, 0.f));
            *reinterpret_cast<float2*>(&C[m0 * 256 + n])       = make_float2(v0, v1);
            *reinterpret_cast<float2*>(&C[(m0 + 8) * 256 + n]) = make_float2(v2, v3);
        }
    }
}

// ---------------------------------------------------------------------------
// Layer-3 GEMM with fused final layer (R6-proven register epilogue)
// ---------------------------------------------------------------------------
__global__ __launch_bounds__(256, 2) void gemm_l3(const float* __restrict__ A,
                                                  const float* __restrict__ Bt,
                                                  const float* __restrict__ bias,
                                                  const float* __restrict__ W4) {
    extern __shared__ char smem[];
    uint32_t sb = smem_u32(smem);
    float* sW4 = (float*)(smem + SMEM_GEMM);
    const int tid = threadIdx.x;
    const int wid = tid >> 5;
    const int lane = tid & 31;
    const int wm = wid >> 2;
    const int wn = wid & 3;
    const size_t bm = (size_t)blockIdx.y * 128;
    const int bn = blockIdx.x * 128;
    const int nit = 8;

    if (tid < 256) {
        sW4[tid * 3 + 0] = W4[tid * 3 + 0];
        sW4[tid * 3 + 1] = W4[tid * 3 + 1];
        sW4[tid * 3 + 2] = W4[tid * 3 + 2];
    }
    __syncthreads();

    float acc[4][4][4];
#pragma unroll
    for (int i = 0; i < 4; i++)
#pragma unroll
        for (int j = 0; j < 4; j++)
#pragma unroll
            for (int v = 0; v < 4; v++) acc[i][j][v] = 0.f;

    load_A(sb, A, bm, 0, 0, 256, tid);  load_B(sb, Bt, bn, 0, 0, 256, tid);  CP_COMMIT();
    load_A(sb, A, bm, 32, 1, 256, tid); load_B(sb, Bt, bn, 32, 1, 256, tid); CP_COMMIT();

    LdsmGeom geo = make_geom(lane, wm, wn);

    for (int it = 0; it < nit; it++) {
        if (it + 1 < nit) { CP_WAIT(1); } else { CP_WAIT(0); }
        __syncthreads();
        if (it + 2 < nit) {
            int stg = (it + 2) % NST;
            load_A(sb, A, bm, (it + 2) * 32, stg, 256, tid);
            load_B(sb, Bt, bn, (it + 2) * 32, stg, 256, tid);
            CP_COMMIT();
        }
        int stg = it % NST;
        mma_block(acc, sb + stg * AST, sb + B_BASE + stg * AST, geo);
    }

    const int er = lane >> 2;
    const int ec = (lane & 3) * 2;
#pragma unroll
    for (int mt = 0; mt < 4; mt++) {
        float p[2][3];
#pragma unroll
        for (int h = 0; h < 2; h++)
#pragma unroll
            for (int c = 0; c < 3; c++) p[h][c] = 0.f;
#pragma unroll
        for (int nt = 0; nt < 4; nt++) {
            int n = bn + wn * 32 + nt * 8 + ec;
            float bi0 = __ldg(&bias[n]);
            float bi1 = __ldg(&bias[n + 1]);
            float v0 = fmaxf(acc[mt][nt][0] + bi0, 0.f);
            float v1 = fmaxf(acc[mt][nt][1] + bi1, 0.f);
            float v2 = fmaxf(acc[mt][nt][2] + bi0, 0.f);
            float v3 = fmaxf(acc[mt][nt][3] + bi1, 0.f);
#pragma unroll
            for (int c = 0; c < 3; c++) {
                float w0 = sW4[n * 3 + c];
                float w1 = sW4[(n + 1) * 3 + c];
                p[0][c] += v0 * w0 + v1 * w1;
                p[1][c] += v2 * w0 + v3 * w1;
            }
        }
#pragma unroll
        for (int h = 0; h < 2; h++)
#pragma unroll
            for (int c = 0; c < 3; c++) {
                p[h][c] += __shfl_xor_sync(0xFFFFFFFFu, p[h][c], 1);
                p[h][c] += __shfl_xor_sync(0xFFFFFFFFu, p[h][c], 2);
            }
        if ((lane & 3) == 0) {
            size_t m0 = bm + wm * 64 + mt * 16 + er;
#pragma unroll
            for (int c = 0; c < 3; c++) {
                atomicAdd(&g_pred[m0 * 3 + c],       p[0][c]);
                atomicAdd(&g_pred[(m0 + 8) * 3 + c], p[1][c]);
            }
        }
    }
}

// ---------------------------------------------------------------------------
// im2col (padded, tf32-rounded)
// ---------------------------------------------------------------------------
__global__ void build_X(const float* __restrict__ mf, const float* __restrict__ mask) {
    int p = blockIdx.x;
    int t = threadIdx.x;
    if (t >= K0P) return;
    int y = p >> 7, x = p & 127;
    float v = 0.f;
    if (t < K1) {
        int c = t / 9, r = t - c * 9;
        int ki = r / 3, kj = r - ki * 3;
        int yy = y + ki - 1, xx = x + kj - 1;
        if (yy >= 0 && yy < FH && xx >= 0 && xx < FW) {
            v = (c < 64) ? mf[(c << 14) + (yy << 7) + xx] : mask[(yy << 7) + xx];
        }
        v = rnd_tf32(v);
    }
    g_X[p * K0P + t] = v;
}

// ---------------------------------------------------------------------------
// Merged prep: transpose+round all 4 weights + zero g_pred, one launch
// ---------------------------------------------------------------------------
#define SEG0 (256 * K0P)            // Wt0
#define SEG1 (256 * 256)
#define PREP_TOT (SEG0 + 3 * SEG1 + SN * 3)
__global__ void prep_all(const float* __restrict__ W0, const float* __restrict__ W1,
                         const float* __restrict__ W2, const float* __restrict__ W3) {
    int i = blockIdx.x * blockDim.x + threadIdx.x;
    if (i >= PREP_TOT) return;
    if (i < SEG0) {
        int n = i / K0P, k = i - n * K0P;
        g_Wt0[i] = (k < K1) ? rnd_tf32(W0[k * 256 + n]) : 0.f;
        return;
    }
    i -= SEG0;
    if (i < SEG1) { int n = i >> 8, k = i & 255; g_Wt1[i] = rnd_tf32(W1[k * 256 + n]); return; }
    i -= SEG1;
    if (i < SEG1) { int n = i >> 8, k = i & 255; g_Wt2[i] = rnd_tf32(W2[k * 256 + n]); return; }
    i -= SEG1;
    if (i < SEG1) { int n = i >> 8, k = i & 255; g_Wt3[i] = rnd_tf32(W3[k * 256 + n]); return; }
    i -= SEG1;
    g_pred[i] = 0.f;
}

// ---------------------------------------------------------------------------
// local ensemble (adds b4)
// ---------------------------------------------------------------------------
__global__ void ensemble(const float* __restrict__ hr, const float* __restrict__ b4,
                         float* __restrict__ out) {
    int q = blockIdx.x * blockDim.x + threadIdx.x;
    if (q >= QN) return;
    float c0 = hr[2 * q], c1 = hr[2 * q + 1];
    float b40 = __ldg(&b4[0]), b41 = __ldg(&b4[1]), b42 = __ldg(&b4[2]);
    float area[4];
#pragma unroll
    for (int cc = 0; cc < 4; cc++) {
        int idx; float r0, r1;
        corner_calc(c0, c1, cc, idx, r0, r1);
        area[cc] = fabsf(r0 * r1) + 1e-9f;
    }
    float tot = area[0] + area[1] + area[2] + area[3];
    float o0 = 0.f, o1 = 0.f, o2 = 0.f;
#pragma unroll
    for (int cc = 0; cc < 4; cc++) {
        float w = area[3 - cc] / tot;
        size_t s = (size_t)cc * QN + q;
        o0 += (g_pred[s * 3 + 0] + b40) * w;
        o1 += (g_pred[s * 3 + 1] + b41) * w;
        o2 += (g_pred[s * 3 + 2] + b42) * w;
    }
    out[0 * QN + q] = o0;
    out[1 * QN + q] = o1;
    out[2 * QN + q] = o2;
}

// ---------------------------------------------------------------------------
// Launch
// ---------------------------------------------------------------------------
extern "C" void kernel_launch(void* const* d_in, const int* in_sizes, int n_in,
                              void* d_out, int out_size) {
    const float* mf   = (const float*)d_in[0];
    const float* mask = (const float*)d_in[1];
    const float* hr = (const float*)d_in[3];
    const float* W0 = (const float*)d_in[4];
    const float* b0 = (const float*)d_in[5];
    const float* W1 = (const float*)d_in[6];
    const float* b1 = (const float*)d_in[7];
    const float* W2 = (const float*)d_in[8];
    const float* b2 = (const float*)d_in[9];
    const float* W3 = (const float*)d_in[10];
    const float* b3 = (const float*)d_in[11];
    const float* W4 = (const float*)d_in[12];
    const float* b4 = (const float*)d_in[13];
    float* out = (float*)d_out;

    void *pX, *pWt0, *pWt1, *pWt2, *pWt3, *pHp, *pA, *pB;
    cudaGetSymbolAddress(&pX,   g_X);
    cudaGetSymbolAddress(&pWt0, g_Wt0);
    cudaGetSymbolAddress(&pWt1, g_Wt1);
    cudaGetSymbolAddress(&pWt2, g_Wt2);
    cudaGetSymbolAddress(&pWt3, g_Wt3);
    cudaGetSymbolAddress(&pHp,  g_hp);
    cudaGetSymbolAddress(&pA,   g_bufA);
    cudaGetSymbolAddress(&pB,   g_bufB);

    cudaFuncSetAttribute(gemm_tf32, cudaFuncAttributeMaxDynamicSharedMemorySize, SMEM_GEMM);
    cudaFuncSetAttribute(gemm_l1,   cudaFuncAttributeMaxDynamicSharedMemorySize, SMEM_L1);
    cudaFuncSetAttribute(gemm_l3,   cudaFuncAttributeMaxDynamicSharedMemorySize, SMEM_L3);

    build_X<<<NPIX, 640>>>(mf, mask);
    prep_all<<<(PREP_TOT + 255) / 256, 256>>>(W0, W1, W2, W3);

    // hp = X @ W0 + b0 (no relu, no round)
    gemm_tf32<<<dim3(2, NPIX / 128), 256, SMEM_GEMM>>>((const float*)pX, (const float*)pWt0,
                                                       b0, (float*)pHp, K0P, 0, 0);

    // layer 1 (fused assemble): -> bufA
    gemm_l1<<<dim3(2, SN / 128), 256, SMEM_L1>>>(hr, W0, (const float*)pWt1, b1, (float*)pA);

    // layer 2: bufA -> bufB
    gemm_tf32<<<dim3(2, SN / 128), 256, SMEM_GEMM>>>((const float*)pA, (const float*)pWt2,
                                                     b2, (float*)pB, 256, 1, 1);

    // layer 3 + final fused: bufB -> g_pred
    gemm_l3<<<dim3(2, SN / 128), 256, SMEM_L3>>>((const float*)pB, (const float*)pWt3,
                                                 b3, W4);

    ensemble<<<QN / 256, 256>>>(hr, b4, out);
}